// round 12
// baseline (speedup 1.0000x reference)
#include <cuda_runtime.h>
#include <cuda_bf16.h>
#include <cstdint>

// GruDirection3d forward wavefront:
//   out[d,y,x] = z*h_tilde + (1-z)*out[d-1,y-1,x-1],  border -> h0
//
// R12 = R10's shfl diagonal-shift compute (validated correct)
//     + R6/R11's direct-LDG depth-4 float4 register prefetch
//     + R11's 512-thread / two independent 256-thread named-barrier domains.
// No z/h smem, no 33-stride tile: the (y-1,x-1) shift of the previous
// plane's output resolves in registers via shfl (rows are 8 lanes apart);
// only each warp's first row reads a float4 from a tiny per-domain 2x8x8
// exchange written by warp last-rows. LSU ops per plane drop ~2x vs R11;
// 96 CTAs = one perfect wave, 16 warps/SM in decoupled barrier domains.

#define PLANE4 256     // float4 per 32x32 plane
#define PD     4

__global__ __launch_bounds__(512, 1)
void gru3d_kernel(const float4* __restrict__ zv,
                  const float4* __restrict__ hv,
                  const float*  __restrict__ h0p,
                  float4*       __restrict__ ov)
{
    __shared__ float4 sb[2][2][8][8];   // [domain][phase][warp-row][x4] = 2KB

    const float h0 = __ldg(h0p);
    const int tid  = threadIdx.x;
    const int dom  = tid >> 8;          // 0/1: which volume
    const int t    = tid & 255;
    const int lane = t & 31;
    const int w    = t >> 5;            // domain-warp 0..7 (= y>>2)
    const int x4   = t & 7;
    const int y    = t >> 3;

    const int vol = blockIdx.x * 2 + dom;
    const size_t base = (size_t)vol * (32 * PLANE4) + (size_t)t;
    const float4* zp = zv + base;
    const float4* hp = hv + base;
    float4*       op = ov + base;

    // Depth-4 register prefetch (planes 0..3 in flight).
    float4 zb[PD], hb[PD];
    #pragma unroll
    for (int s = 0; s < PD; ++s) {
        zb[s] = zp[(size_t)s * PLANE4];
        hb[s] = hp[(size_t)s * PLANE4];
    }

    const int rcl = (w > 0) ? (w - 1) : 0;   // exchange row to read (clamped)
    const int bid = 1 + dom;                 // named barrier id per domain
    float4 o = make_float4(0.f, 0.f, 0.f, 0.f);   // prev-plane output

    #pragma unroll
    for (int d = 0; d < 32; ++d) {
        const int s = d & (PD - 1);
        const float4 zd = zb[s];
        const float4 hd = hb[s];
        if (d + PD < 32) {
            zb[s] = zp[(size_t)(d + PD) * PLANE4];
            hb[s] = hp[(size_t)(d + PD) * PLANE4];
        }

        // Shifted prev-plane values: register path (rows are 8 lanes apart).
        const float ux = __shfl_up_sync(0xffffffffu, o.x, 8);
        const float uy = __shfl_up_sync(0xffffffffu, o.y, 8);
        const float uz = __shfl_up_sync(0xffffffffu, o.z, 8);
        const float b9 = __shfl_up_sync(0xffffffffu, o.w, 9);
        // Warp-boundary path: row y-1 lives in the exchange (prev warp's
        // last row, written at plane d-1; visible via the d-1 barrier).
        const float4 sv  = sb[dom][(d + 1) & 1][rcl][x4];
        const float  sbw = __shfl_up_sync(0xffffffffu, sv.w, 1);

        const bool frow = (lane < 8);    // y%4==0: smem path
        float p0 = frow ? sbw  : b9;
        float p1 = frow ? sv.x : ux;
        float p2 = frow ? sv.y : uy;
        float p3 = frow ? sv.z : uz;
        if (x4 == 0) p0 = h0;                        // x-1 < 0 border
        if (y == 0 || d == 0) { p0 = h0; p1 = h0; p2 = h0; p3 = h0; }

        o.x = fmaf(zd.x, hd.x - p0, p0);
        o.y = fmaf(zd.y, hd.y - p1, p1);
        o.z = fmaf(zd.z, hd.z - p2, p2);
        o.w = fmaf(zd.w, hd.w - p3, p3);

        op[(size_t)d * PLANE4] = o;
        if (lane >= 24) sb[dom][d & 1][w][x4] = o;   // rows y%4==3 -> exchange

        // Domain-local barrier (256 threads): plane-d exchange writes
        // visible before plane d+1 reads. Slots alternate by d&1, so the
        // write at d+1 never races the reads at d+1 (they target d&1... the
        // other phase).
        asm volatile("bar.sync %0, 256;" :: "r"(bid) : "memory");
    }
}

extern "C" void kernel_launch(void* const* d_in, const int* in_sizes, int n_in,
                              void* d_out, int out_size)
{
    const float4* z  = (const float4*)d_in[0];
    const float4* ht = (const float4*)d_in[1];
    const float*  h0 = (const float*)d_in[2];
    float4* out = (float4*)d_out;

    const int n_volumes = out_size / (32 * PLANE4 * 4);   // B*C = 192
    gru3d_kernel<<<n_volumes / 2, 512>>>(z, ht, h0, out);
}

// round 13
// speedup vs baseline: 1.1754x; 1.1754x over previous
#include <cuda_runtime.h>
#include <cuda_bf16.h>
#include <cstdint>

// GruDirection3d forward wavefront:
//   out[d,y,x] = z*h_tilde + (1-z)*out[d-1,y-1,x-1],  border -> h0
//
// R13: LSU-port-minimized plane sweep. 512 threads = 2 independent 256-thread
// domains (named barriers), 2 volumes/CTA, 96 CTAs = one wave (R11 frame).
// Per domain, a 5-slot LINEAR 32x32 float staging ring serves BOTH the
// diagonal dependency exchange and the output path:
//   - thread (y=t>>3, x4=t&7) STS.128 its float4 at chunk t: lanes 0-7 of a
//     phase cover one 128B row -> conflict-free (4 cyc/warp).
//   - prev (y-1,x-1) read = 2 LDS.128: chunk B=(y-1)*8+x4 (p1..p3=B.xyz),
//     chunk A=B-1 (p0=A.w). Each 8-lane phase spans one 128B row-segment ->
//     conflict-free.
//   - output plane leaves via ONE cp.async.bulk S->G (4KB) per plane,
//     replacing 16 STG.128 (192 cyc of LSU issue) with ~1 op.
// Ring safety (R=5, wait_group(3)): warps overwrite slot (d+1)%5 knowing (via
// plane-d barrier) t0's plane-(d-1) wait_group(3) -> DMA group d-4 done; slot
// (d+1)%5's previous DMA is group d-4. Readers of slot s as "prev" ran 4
// planes before its rewrite, separated by barriers.
// z/h_tilde stay as depth-4 float4 register LDG prefetch (proven).

#define PLANE4 256     // float4 per 32x32 plane
#define PD     4
#define RING   5

__device__ __forceinline__ void bulk_s2g(const void* g, unsigned int s) {
    asm volatile("cp.async.bulk.global.shared::cta.bulk_group [%0], [%1], 4096;"
                 :: "l"(g), "r"(s) : "memory");
}

__global__ __launch_bounds__(512, 1)
void gru3d_kernel(const float4* __restrict__ zv,
                  const float4* __restrict__ hv,
                  const float*  __restrict__ h0p,
                  float4*       __restrict__ ov)
{
    __shared__ __align__(16) float4 stg[2][RING][PLANE4];   // 40KB

    const float h0 = __ldg(h0p);
    const int tid = threadIdx.x;
    const int dom = tid >> 8;           // 0/1: which volume
    const int t   = tid & 255;
    const int y   = t >> 3;
    const int x4  = t & 7;

    const int vol = blockIdx.x * 2 + dom;
    const size_t base = (size_t)vol * (32 * PLANE4) + (size_t)t;
    const float4* zp = zv + base;
    const float4* hp = hv + base;
    float4* const ovol = ov + (size_t)vol * (32 * PLANE4);   // plane-major out

    // Depth-4 register prefetch (planes 0..3 in flight).
    float4 zb[PD], hb[PD];
    #pragma unroll
    for (int s = 0; s < PD; ++s) {
        zb[s] = zp[(size_t)s * PLANE4];
        hb[s] = hp[(size_t)s * PLANE4];
    }

    // Prev-plane read chunks (conflict-free per 8-lane phase).
    const int ry = (y > 0) ? (y - 1) : 0;
    const int cB = ry * 8 + x4;
    const int cA = (cB > 0) ? (cB - 1) : 0;
    const int bid = 1 + dom;            // named barrier per domain

    #pragma unroll
    for (int d = 0; d < 32; ++d) {
        const int s = d & (PD - 1);
        const float4 zd = zb[s];
        const float4 hd = hb[s];
        if (d + PD < 32) {
            zb[s] = zp[(size_t)(d + PD) * PLANE4];
            hb[s] = hp[(size_t)(d + PD) * PLANE4];
        }

        // prev = out[d-1] shifted by (+1,+1); slot (d-1)%RING == (d+4)%RING.
        const float4* pv = &stg[dom][(d + RING - 1) % RING][0];
        const float4 A = pv[cA];
        const float4 B = pv[cB];

        float p0 = A.w, p1 = B.x, p2 = B.y, p3 = B.z;
        if (x4 == 0) p0 = h0;                         // x-1 < 0 border
        if (y == 0 || d == 0) { p0 = h0; p1 = h0; p2 = h0; p3 = h0; }

        float4 o;
        o.x = fmaf(zd.x, hd.x - p0, p0);
        o.y = fmaf(zd.y, hd.y - p1, p1);
        o.z = fmaf(zd.z, hd.z - p2, p2);
        o.w = fmaf(zd.w, hd.w - p3, p3);

        stg[dom][d % RING][t] = o;      // STS.128, consecutive chunks

        asm volatile("bar.sync %0, 256;" :: "r"(bid) : "memory");

        if (t == 0) {
            asm volatile("fence.proxy.async.shared::cta;" ::: "memory");
            unsigned int sa =
                (unsigned int)__cvta_generic_to_shared(&stg[dom][d % RING][0]);
            bulk_s2g(ovol + (size_t)d * PLANE4, sa);
            asm volatile("cp.async.bulk.commit_group;" ::: "memory");
            asm volatile("cp.async.bulk.wait_group 3;" ::: "memory");
        }
    }

    // Drain all outstanding bulk stores before CTA exit.
    if (t == 0) {
        asm volatile("cp.async.bulk.wait_group 0;" ::: "memory");
    }
    asm volatile("bar.sync %0, 256;" :: "r"(bid) : "memory");
}

extern "C" void kernel_launch(void* const* d_in, const int* in_sizes, int n_in,
                              void* d_out, int out_size)
{
    const float4* z  = (const float4*)d_in[0];
    const float4* ht = (const float4*)d_in[1];
    const float*  h0 = (const float*)d_in[2];
    float4* out = (float4*)d_out;

    const int n_volumes = out_size / (32 * PLANE4 * 4);   // B*C = 192
    gru3d_kernel<<<n_volumes / 2, 512>>>(z, ht, h0, out);
}